// round 4
// baseline (speedup 1.0000x reference)
#include <cuda_runtime.h>
#include <cuda_bf16.h>
#include <math.h>
#include <stdint.h>

#define B  1024
#define S  200
#define HD 256
#define AD 128

// ---------------- scratch (static device globals; no allocations) ----------
__device__ float g_tproj[B * AD];
__device__ float g_scores[B * S];
__device__ float g_att[S * B];                         // att transposed [t][b]
__device__ __align__(16) float g_X[3ull * S * B * HD]; // [gate][t][b][h]
__device__ __align__(16) float g_h[B * HD];            // h fp32 (master)
__device__ __align__(16) float g_z[B * HD];
__device__ unsigned int g_grpbar[16];

// bf16 split operands for tensor-core GEMMs
__device__ __align__(16) __nv_bfloat16 g_hsh[(size_t)B * S * HD];
__device__ __align__(16) __nv_bfloat16 g_hsl[(size_t)B * S * HD];
__device__ __align__(16) __nv_bfloat16 g_Wxh[768 * 256];   // [Wr;Wz;Wn] x-part
__device__ __align__(16) __nv_bfloat16 g_Wxl[768 * 256];
__device__ __align__(16) __nv_bfloat16 g_Whh[768 * 256];   // [Wr;Wz;Wn] h-part
__device__ __align__(16) __nv_bfloat16 g_Whl[768 * 256];
__device__ __align__(16) __nv_bfloat16 g_Wsh[128 * 256];   // W1 hidden part
__device__ __align__(16) __nv_bfloat16 g_Wsl[128 * 256];
// recurrence state as bf16 split
__device__ __align__(16) __nv_bfloat16 g_hh[B * HD];
__device__ __align__(16) __nv_bfloat16 g_hl[B * HD];
__device__ __align__(16) __nv_bfloat16 g_rhh[B * HD];
__device__ __align__(16) __nv_bfloat16 g_rhl[B * HD];

static const size_t TB  = (size_t)B * HD;            // 262144
static const size_t XSZ = (size_t)S * B * HD;        // 52,428,800

__device__ __forceinline__ float sigf(float x) { return 1.0f / (1.0f + expf(-x)); }

__device__ __forceinline__ uint32_t smem_u32(const void* p) {
    uint32_t a;
    asm("{ .reg .u64 t; cvta.to.shared.u64 t, %1; cvt.u32.u64 %0, t; }"
        : "=r"(a) : "l"(p));
    return a;
}

__device__ __forceinline__ void ldmat4(uint32_t a[4], uint32_t addr) {
    asm volatile("ldmatrix.sync.aligned.m8n8.x4.shared.b16 {%0,%1,%2,%3}, [%4];"
                 : "=r"(a[0]), "=r"(a[1]), "=r"(a[2]), "=r"(a[3]) : "r"(addr));
}

#define MMA16816(d, a, bb) \
    asm volatile("mma.sync.aligned.m16n8k16.row.col.f32.bf16.bf16.f32 " \
        "{%0,%1,%2,%3}, {%4,%5,%6,%7}, {%8,%9}, {%0,%1,%2,%3};" \
        : "+f"((d)[0]), "+f"((d)[1]), "+f"((d)[2]), "+f"((d)[3]) \
        : "r"((a)[0]), "r"((a)[1]), "r"((a)[2]), "r"((a)[3]), \
          "r"((bb)[0]), "r"((bb)[1]))

// ---------------- reset barrier counters -----------------------------------
__global__ void k_reset() { if (threadIdx.x < 16) g_grpbar[threadIdx.x] = 0u; }

// ---------------- split fp32 -> bf16 hi/lo ----------------------------------
__global__ void k_cvt_hs(const float* __restrict__ hs) {
    size_t i = (size_t)blockIdx.x * 256 + threadIdx.x;   // float4 index
    float4 v = ((const float4*)hs)[i];
    union { __nv_bfloat16 b[4]; uint2 u; } H, L;
    H.b[0] = __float2bfloat16(v.x); L.b[0] = __float2bfloat16(v.x - __bfloat162float(H.b[0]));
    H.b[1] = __float2bfloat16(v.y); L.b[1] = __float2bfloat16(v.y - __bfloat162float(H.b[1]));
    H.b[2] = __float2bfloat16(v.z); L.b[2] = __float2bfloat16(v.z - __bfloat162float(H.b[2]));
    H.b[3] = __float2bfloat16(v.w); L.b[3] = __float2bfloat16(v.w - __bfloat162float(H.b[3]));
    ((uint2*)g_hsh)[i] = H.u;
    ((uint2*)g_hsl)[i] = L.u;
}

__global__ void k_cvt_w(const float* __restrict__ Wr, const float* __restrict__ Wz,
                        const float* __restrict__ Wn, const float* __restrict__ W1) {
    int row = blockIdx.x, k = threadIdx.x;
    if (row < 768) {
        int g = row >> 8, c = row & 255;
        const float* W = (g == 0) ? Wr : (g == 1) ? Wz : Wn;
        float v = W[c * 512 + k];
        __nv_bfloat16 h = __float2bfloat16(v);
        g_Wxh[row * 256 + k] = h;
        g_Wxl[row * 256 + k] = __float2bfloat16(v - __bfloat162float(h));
        float v2 = W[c * 512 + 256 + k];
        __nv_bfloat16 h2 = __float2bfloat16(v2);
        g_Whh[row * 256 + k] = h2;
        g_Whl[row * 256 + k] = __float2bfloat16(v2 - __bfloat162float(h2));
    } else {
        int a = row - 768;
        float v = W1[a * 512 + k];
        __nv_bfloat16 h = __float2bfloat16(v);
        g_Wsh[a * 256 + k] = h;
        g_Wsl[a * 256 + k] = __float2bfloat16(v - __bfloat162float(h));
    }
}

// ---------------- tproj[b,a] = b1[a] + sum_d tgt[b,d]*W1[a,256+d] ----------
__global__ void k_tproj(const float* __restrict__ tgt,
                        const float* __restrict__ W1,
                        const float* __restrict__ b1) {
    __shared__ float4 ts[64];
    int b = blockIdx.x, a = threadIdx.x;
    if (a < 64) ts[a] = ((const float4*)(tgt + (size_t)b * HD))[a];
    __syncthreads();
    const float4* w = (const float4*)(W1 + (size_t)a * 512 + 256);
    float s0 = 0.f, s1 = 0.f, s2 = 0.f, s3 = 0.f;
#pragma unroll
    for (int k = 0; k < 64; k += 4) {
        float4 wv, tv;
        wv = w[k];     tv = ts[k];     s0 += wv.x*tv.x + wv.y*tv.y + wv.z*tv.z + wv.w*tv.w;
        wv = w[k + 1]; tv = ts[k + 1]; s1 += wv.x*tv.x + wv.y*tv.y + wv.z*tv.z + wv.w*tv.w;
        wv = w[k + 2]; tv = ts[k + 2]; s2 += wv.x*tv.x + wv.y*tv.y + wv.z*tv.z + wv.w*tv.w;
        wv = w[k + 3]; tv = ts[k + 3]; s3 += wv.x*tv.x + wv.y*tv.y + wv.z*tv.z + wv.w*tv.w;
    }
    g_tproj[b * AD + a] = b1[a] + ((s0 + s1) + (s2 + s3));
}

// =========== mma.sync bf16-split GEMM mainloop (128x128, Klog=768) =========
__device__ __forceinline__ void gemm_ml(
    const __nv_bfloat16* __restrict__ Ah, const __nv_bfloat16* __restrict__ Al,
    const __nv_bfloat16* __restrict__ Bh, const __nv_bfloat16* __restrict__ Bl,
    __nv_bfloat16* smA, __nv_bfloat16* smB, float c[2][8][4])
{
    int tid = threadIdx.x, lane = tid & 31, wid = tid >> 5;
    int m0 = (wid & 3) * 32, n0 = (wid >> 2) * 64;
    uint32_t smA_u = smem_u32(smA);
    int r0 = tid >> 2, q = tid & 3;

    uint4 ra0, ra1, rb0, rb1;
    ra0 = *(const uint4*)(Ah + r0 * 256 + q * 8);
    ra1 = *(const uint4*)(Ah + (r0 + 64) * 256 + q * 8);
    rb0 = *(const uint4*)(Bh + r0 * 256 + q * 8);
    rb1 = *(const uint4*)(Bh + (r0 + 64) * 256 + q * 8);
    *(uint4*)(smA + r0 * 40 + q * 8)        = ra0;
    *(uint4*)(smA + (r0 + 64) * 40 + q * 8) = ra1;
    *(uint4*)(smB + r0 * 40 + q * 8)        = rb0;
    *(uint4*)(smB + (r0 + 64) * 40 + q * 8) = rb1;
    __syncthreads();

    for (int kc = 0; kc < 24; kc++) {
        if (kc < 23) {
            int kn = kc + 1;
            const __nv_bfloat16* As = (kn < 16) ? Ah : Al;
            const __nv_bfloat16* Bs = (kn < 8) ? Bh : (kn < 16 ? Bl : Bh);
            int k0 = (kn & 7) * 32;
            ra0 = *(const uint4*)(As + r0 * 256 + k0 + q * 8);
            ra1 = *(const uint4*)(As + (r0 + 64) * 256 + k0 + q * 8);
            rb0 = *(const uint4*)(Bs + r0 * 256 + k0 + q * 8);
            rb1 = *(const uint4*)(Bs + (r0 + 64) * 256 + k0 + q * 8);
        }
        const __nv_bfloat16* bufB = smB + (kc & 1) * 5120;
        uint32_t abase = smA_u + (kc & 1) * 10240
                       + (uint32_t)(m0 + (lane & 15)) * 80 + ((lane >> 4) * 8) * 2;
#pragma unroll
        for (int ks = 0; ks < 2; ks++) {
            uint32_t af0[4], af1[4];
            ldmat4(af0, abase + ks * 32);
            ldmat4(af1, abase + 16 * 80 + ks * 32);
            uint32_t bfr[8][2];
#pragma unroll
            for (int nf = 0; nf < 8; nf++) {
                const uint32_t* bp = (const uint32_t*)
                    (bufB + (n0 + nf * 8 + (lane >> 2)) * 40 + ks * 16 + (lane & 3) * 2);
                bfr[nf][0] = bp[0];
                bfr[nf][1] = bp[4];
            }
#pragma unroll
            for (int nf = 0; nf < 8; nf++) {
                MMA16816(c[0][nf], af0, bfr[nf]);
                MMA16816(c[1][nf], af1, bfr[nf]);
            }
        }
        if (kc < 23) {
            int nb = (kc + 1) & 1;
            *(uint4*)(smA + nb * 5120 + r0 * 40 + q * 8)        = ra0;
            *(uint4*)(smA + nb * 5120 + (r0 + 64) * 40 + q * 8) = ra1;
            *(uint4*)(smB + nb * 5120 + r0 * 40 + q * 8)        = rb0;
            *(uint4*)(smB + nb * 5120 + (r0 + 64) * 40 + q * 8) = rb1;
            __syncthreads();
        }
    }
}

// ---------------- X projection via mma.sync --------------------------------
__global__ void __launch_bounds__(256) k_xproj_mma(
    const float* __restrict__ br, const float* __restrict__ bz,
    const float* __restrict__ bn) {
    extern __shared__ __align__(16) char dsm[];
    __nv_bfloat16* smA = (__nv_bfloat16*)dsm;
    __nv_bfloat16* smB = smA + 2 * 5120;
    int ntile = blockIdx.x % 6, mtile = blockIdx.x / 6;

    float c[2][8][4];
#pragma unroll
    for (int i = 0; i < 2; i++)
#pragma unroll
        for (int j = 0; j < 8; j++)
#pragma unroll
            for (int e = 0; e < 4; e++) c[i][j][e] = 0.0f;

    gemm_ml(g_hsh + (size_t)mtile * 128 * 256, g_hsl + (size_t)mtile * 128 * 256,
            g_Wxh + (size_t)ntile * 128 * 256, g_Wxl + (size_t)ntile * 128 * 256,
            smA, smB, c);

    int lane = threadIdx.x & 31, wid = threadIdx.x >> 5;
    int m0 = (wid & 3) * 32, n0 = (wid >> 2) * 64;
    int g = ntile >> 1, h0 = (ntile & 1) * 128;
    const float* bias = (g == 0) ? br : (g == 1) ? bz : bn;
    float2 bv[8];
#pragma unroll
    for (int nf = 0; nf < 8; nf++)
        bv[nf] = *(const float2*)(bias + h0 + n0 + nf * 8 + (lane & 3) * 2);

#pragma unroll
    for (int mf = 0; mf < 2; mf++)
#pragma unroll
        for (int p = 0; p < 2; p++) {
            int rg = mtile * 128 + m0 + mf * 16 + (lane >> 2) + p * 8;
            int b = rg / 200, s = rg - b * 200;
            float* dst = g_X + (size_t)g * XSZ + ((size_t)s * B + b) * 256 + h0;
#pragma unroll
            for (int nf = 0; nf < 8; nf++) {
                float2 o;
                o.x = c[mf][nf][2 * p + 0] + bv[nf].x;
                o.y = c[mf][nf][2 * p + 1] + bv[nf].y;
                *(float2*)(dst + n0 + nf * 8 + (lane & 3) * 2) = o;
            }
        }
}

// ---------------- attention scores via mma.sync ----------------------------
__global__ void __launch_bounds__(256) k_scores_mma(const float* __restrict__ W2) {
    extern __shared__ __align__(16) char dsm[];
    __nv_bfloat16* smA = (__nv_bfloat16*)dsm;
    __nv_bfloat16* smB = smA + 2 * 5120;
    float* Sres = (float*)(dsm + 40960);          // [128][132]
    float* red  = (float*)(dsm + 40960 + 67584);  // [128][2]
    int mtile = blockIdx.x;

    float c[2][8][4];
#pragma unroll
    for (int i = 0; i < 2; i++)
#pragma unroll
        for (int j = 0; j < 8; j++)
#pragma unroll
            for (int e = 0; e < 4; e++) c[i][j][e] = 0.0f;

    gemm_ml(g_hsh + (size_t)mtile * 128 * 256, g_hsl + (size_t)mtile * 128 * 256,
            g_Wsh, g_Wsl, smA, smB, c);

    int tid = threadIdx.x, lane = tid & 31, wid = tid >> 5;
    int m0 = (wid & 3) * 32, n0 = (wid >> 2) * 64;
#pragma unroll
    for (int mf = 0; mf < 2; mf++)
#pragma unroll
        for (int nf = 0; nf < 8; nf++) {
            int r0 = m0 + mf * 16 + (lane >> 2);
            int cc = n0 + nf * 8 + (lane & 3) * 2;
            Sres[r0 * 132 + cc]           = c[mf][nf][0];
            Sres[r0 * 132 + cc + 1]       = c[mf][nf][1];
            Sres[(r0 + 8) * 132 + cc]     = c[mf][nf][2];
            Sres[(r0 + 8) * 132 + cc + 1] = c[mf][nf][3];
        }
    __syncthreads();

    {
        int row = tid >> 1, half = tid & 1;
        int rg = mtile * 128 + row;
        int b = rg / 200;
        const float* tp = g_tproj + b * AD + half * 64;
        const float* w2 = W2 + half * 64;
        float part = 0.0f;
#pragma unroll 8
        for (int j = 0; j < 64; j++)
            part += fmaxf(Sres[row * 132 + half * 64 + j] + tp[j], 0.0f) * w2[j];
        red[row * 2 + half] = part;
    }
    __syncthreads();
    if (tid < 128)
        g_scores[mtile * 128 + tid] = red[tid * 2] + red[tid * 2 + 1];
}

// ---------------- masked softmax over S, output transposed [t][b] ----------
__global__ void k_softmax(const int* __restrict__ lengths) {
    __shared__ float red[256];
    int b = blockIdx.x, s = threadIdx.x;
    int len = lengths[b];
    float sc = -3.0e38f;
    if (s < S) sc = (s < len) ? g_scores[b * S + s] : -1e9f;
    red[s] = sc; __syncthreads();
    for (int o = 128; o; o >>= 1) {
        if (s < o) red[s] = fmaxf(red[s], red[s + o]);
        __syncthreads();
    }
    float mx = red[0]; __syncthreads();
    float e = (s < S) ? expf(sc - mx) : 0.0f;
    red[s] = e; __syncthreads();
    for (int o = 128; o; o >>= 1) {
        if (s < o) red[s] += red[s + o];
        __syncthreads();
    }
    float inv = 1.0f / red[0];
    if (s < S) g_att[s * B + b] = e * inv;
}

// =================== persistent AUGRU scan (mma.sync) ======================
// 128 CTAs = 16 row-groups (64 batch rows) x 8 col-tiles.
// phase1: [r|z](1024x512) = h @ [Wr_h;Wz_h]^T  (CTA tile 64x64)
// phase2: n(1024x256) = rh @ Wn_h^T            (CTA tile 64x32)
// h/rh as bf16 hi/lo (3-term split, Klog=768), weights persistent in smem.
#define P1W 16896   // 64*264
#define P2W 8448    // 32*264

__device__ __forceinline__ void grpbar(int grp, unsigned int target) {
    __threadfence();
    __syncthreads();
    if (threadIdx.x == 0) {
        atomicAdd(&g_grpbar[grp], 1u);
        while (*(volatile unsigned int*)&g_grpbar[grp] < target) { }
        __threadfence();
    }
    __syncthreads();
}

__global__ void __launch_bounds__(256, 1) k_recur2(float* __restrict__ out) {
    extern __shared__ __align__(16) __nv_bfloat16 sm[];
    __nv_bfloat16* Wp1h = sm;                    // [64][264]
    __nv_bfloat16* Wp1l = sm + P1W;
    __nv_bfloat16* Wp2h = sm + 2 * P1W;          // [32][264]
    __nv_bfloat16* Wp2l = sm + 2 * P1W + P2W;
    __nv_bfloat16* Ash  = sm + 2 * P1W + 2 * P2W; // [64][264]
    __nv_bfloat16* Asl  = Ash + P1W;

    int tid = threadIdx.x, lane = tid & 31, wid = tid >> 5;
    int bid = blockIdx.x;
    int rt = bid >> 3, ct = bid & 7;
    int mw = wid & 1, nw = wid >> 1;
    int m0w = mw * 32;

    // persistent weights: phase1 rows ct*64.. of [Wr_h;Wz_h]; phase2 rows 512+ct*32 (Wn_h)
    for (int i = tid; i < 2048; i += 256) {
        int r = i >> 5, u = i & 31;
        *(uint4*)&Wp1h[r * 264 + u * 8] = *(const uint4*)&g_Whh[(size_t)(ct * 64 + r) * 256 + u * 8];
        *(uint4*)&Wp1l[r * 264 + u * 8] = *(const uint4*)&g_Whl[(size_t)(ct * 64 + r) * 256 + u * 8];
    }
    for (int i = tid; i < 1024; i += 256) {
        int r = i >> 5, u = i & 31;
        *(uint4*)&Wp2h[r * 264 + u * 8] = *(const uint4*)&g_Whh[(size_t)(512 + ct * 32 + r) * 256 + u * 8];
        *(uint4*)&Wp2l[r * 264 + u * 8] = *(const uint4*)&g_Whl[(size_t)(512 + ct * 32 + r) * 256 + u * 8];
    }
    // zero h state (each CTA zeroes 8 rows of its group's 64)
    {
        int r0 = rt * 64 + ct * 8;
        float4 zf = make_float4(0.f, 0.f, 0.f, 0.f);
        uint4 zu = make_uint4(0u, 0u, 0u, 0u);
        float4* hp = (float4*)(g_h + (size_t)r0 * 256);
        uint4* hhp = (uint4*)(g_hh + (size_t)r0 * 256);
        uint4* hlp = (uint4*)(g_hl + (size_t)r0 * 256);
        for (int i = tid; i < 512; i += 256) hp[i] = zf;
        for (int i = tid; i < 256; i += 256) { hhp[i] = zu; hlp[i] = zu; }
    }
    unsigned int tcnt = 8;
    grpbar(rt, tcnt); tcnt += 8;

    uint32_t AshU = smem_u32(Ash), AslU = smem_u32(Asl);

    for (int t = 0; t < S; t++) {
        // ---------- phase 1: load h tile, GEMM 64x64xK768 ----------
        for (int i = tid; i < 2048; i += 256) {
            int r = i >> 5, u = i & 31;
            int4 vh = __ldcg((const int4*)&g_hh[(size_t)(rt * 64 + r) * 256 + u * 8]);
            int4 vl = __ldcg((const int4*)&g_hl[(size_t)(rt * 64 + r) * 256 + u * 8]);
            *(int4*)&Ash[r * 264 + u * 8] = vh;
            *(int4*)&Asl[r * 264 + u * 8] = vl;
        }
        __syncthreads();

        float c1[2][2][4];
#pragma unroll
        for (int i = 0; i < 2; i++)
#pragma unroll
            for (int j = 0; j < 2; j++)
#pragma unroll
                for (int e = 0; e < 4; e++) c1[i][j][e] = 0.0f;
        {
            int n0w = nw * 16;
#pragma unroll
            for (int pass = 0; pass < 3; pass++) {
                uint32_t Abase = (pass == 1) ? AslU : AshU;
                const __nv_bfloat16* Wp = (pass == 2) ? Wp1l : Wp1h;
                uint32_t ab = Abase + (uint32_t)(m0w + (lane & 15)) * 528 + ((lane >> 4) * 8) * 2;
#pragma unroll
                for (int kc = 0; kc < 16; kc++) {
                    int k0 = kc * 16;
                    uint32_t af0[4], af1[4];
                    ldmat4(af0, ab + k0 * 2);
                    ldmat4(af1, ab + 16 * 528 + k0 * 2);
#pragma unroll
                    for (int nf = 0; nf < 2; nf++) {
                        const uint32_t* bp = (const uint32_t*)
                            (Wp + (n0w + nf * 8 + (lane >> 2)) * 264 + k0 + (lane & 3) * 2);
                        uint32_t bf2[2] = { bp[0], bp[4] };
                        MMA16816(c1[0][nf], af0, bf2);
                        MMA16816(c1[1][nf], af1, bf2);
                    }
                }
            }
        }
        // ---------- phase 1 epilogue ----------
        if (ct < 4) {
            // r gate -> rh = sigmoid(c + Xr)*h, split to bf16 hi/lo
            const float* Xr = g_X + (size_t)t * TB;
#pragma unroll
            for (int mf = 0; mf < 2; mf++)
#pragma unroll
                for (int p = 0; p < 2; p++) {
                    int m = m0w + mf * 16 + (lane >> 2) + p * 8;
                    int b = rt * 64 + m;
#pragma unroll
                    for (int nf = 0; nf < 2; nf++) {
                        int gc = ct * 64 + nw * 16 + nf * 8 + (lane & 3) * 2;
                        float2 xv = *(const float2*)&Xr[(size_t)b * 256 + gc];
                        float h0 = __bfloat162float(Ash[m * 264 + gc])
                                 + __bfloat162float(Asl[m * 264 + gc]);
                        float h1 = __bfloat162float(Ash[m * 264 + gc + 1])
                                 + __bfloat162float(Asl[m * 264 + gc + 1]);
                        float rh0 = sigf(c1[mf][nf][2 * p] + xv.x) * h0;
                        float rh1 = sigf(c1[mf][nf][2 * p + 1] + xv.y) * h1;
                        __nv_bfloat162 hi, lo;
                        hi.x = __float2bfloat16(rh0);
                        hi.y = __float2bfloat16(rh1);
                        lo.x = __float2bfloat16(rh0 - __bfloat162float(hi.x));
                        lo.y = __float2bfloat16(rh1 - __bfloat162float(hi.y));
                        *(__nv_bfloat162*)&g_rhh[(size_t)b * 256 + gc] = hi;
                        *(__nv_bfloat162*)&g_rhl[(size_t)b * 256 + gc] = lo;
                    }
                }
        } else {
            // z gate -> z = sigmoid(c + Xz)*att
            const float* Xz = g_X + XSZ + (size_t)t * TB;
#pragma unroll
            for (int mf = 0; mf < 2; mf++)
#pragma unroll
                for (int p = 0; p < 2; p++) {
                    int m = m0w + mf * 16 + (lane >> 2) + p * 8;
                    int b = rt * 64 + m;
                    float av = g_att[t * B + b];
#pragma unroll
                    for (int nf = 0; nf < 2; nf++) {
                        int gc = (ct - 4) * 64 + nw * 16 + nf * 8 + (lane & 3) * 2;
                        float2 xv = *(const float2*)&Xz[(size_t)b * 256 + gc];
                        float2 o;
                        o.x = sigf(c1[mf][nf][2 * p] + xv.x) * av;
                        o.y = sigf(c1[mf][nf][2 * p + 1] + xv.y) * av;
                        *(float2*)&g_z[(size_t)b * 256 + gc] = o;
                    }
                }
        }
        grpbar(rt, tcnt); tcnt += 8;

        // ---------- phase 2: load rh tile, GEMM 64x32xK768 ----------
        for (int i = tid; i < 2048; i += 256) {
            int r = i >> 5, u = i & 31;
            int4 vh = __ldcg((const int4*)&g_rhh[(size_t)(rt * 64 + r) * 256 + u * 8]);
            int4 vl = __ldcg((const int4*)&g_rhl[(size_t)(rt * 64 + r) * 256 + u * 8]);
            *(int4*)&Ash[r * 264 + u * 8] = vh;
            *(int4*)&Asl[r * 264 + u * 8] = vl;
        }
        __syncthreads();

        float c2[2][4];
#pragma unroll
        for (int i = 0; i < 2; i++)
#pragma unroll
            for (int e = 0; e < 4; e++) c2[i][e] = 0.0f;
        {
            int n0w = nw * 8;
#pragma unroll
            for (int pass = 0; pass < 3; pass++) {
                uint32_t Abase = (pass == 1) ? AslU : AshU;
                const __nv_bfloat16* Wp = (pass == 2) ? Wp2l : Wp2h;
                uint32_t ab = Abase + (uint32_t)(m0w + (lane & 15)) * 528 + ((lane >> 4) * 8) * 2;
#pragma unroll
                for (int kc = 0; kc < 16; kc++) {
                    int k0 = kc * 16;
                    uint32_t af0[4], af1[4];
                    ldmat4(af0, ab + k0 * 2);
                    ldmat4(af1, ab + 16 * 528 + k0 * 2);
                    const uint32_t* bp = (const uint32_t*)
                        (Wp + (n0w + (lane >> 2)) * 264 + k0 + (lane & 3) * 2);
                    uint32_t bf2[2] = { bp[0], bp[4] };
                    MMA16816(c2[0], af0, bf2);
                    MMA16816(c2[1], af1, bf2);
                }
            }
        }
        // ---------- phase 2 epilogue: n = tanh(c + Xn); h update ----------
        {
            const float* Xn = g_X + 2 * XSZ + (size_t)t * TB;
#pragma unroll
            for (int mf = 0; mf < 2; mf++)
#pragma unroll
                for (int p = 0; p < 2; p++) {
                    int m = m0w + mf * 16 + (lane >> 2) + p * 8;
                    int b = rt * 64 + m;
                    int gc = ct * 32 + nw * 8 + (lane & 3) * 2;
                    float2 xv = *(const float2*)&Xn[(size_t)b * 256 + gc];
                    float n0 = tanhf(c2[mf][2 * p] + xv.x);
                    float n1 = tanhf(c2[mf][2 * p + 1] + xv.y);
                    float2 hv, zv;
                    hv.x = __ldcg(&g_h[(size_t)b * 256 + gc]);
                    hv.y = __ldcg(&g_h[(size_t)b * 256 + gc + 1]);
                    zv.x = __ldcg(&g_z[(size_t)b * 256 + gc]);
                    zv.y = __ldcg(&g_z[(size_t)b * 256 + gc + 1]);
                    float2 o;
                    o.x = hv.x + zv.x * (n0 - hv.x);
                    o.y = hv.y + zv.y * (n1 - hv.y);
                    *(float2*)&g_h[(size_t)b * 256 + gc] = o;
                    __nv_bfloat162 hi, lo;
                    hi.x = __float2bfloat16(o.x);
                    hi.y = __float2bfloat16(o.y);
                    lo.x = __float2bfloat16(o.x - __bfloat162float(hi.x));
                    lo.y = __float2bfloat16(o.y - __bfloat162float(hi.y));
                    *(__nv_bfloat162*)&g_hh[(size_t)b * 256 + gc] = hi;
                    *(__nv_bfloat162*)&g_hl[(size_t)b * 256 + gc] = lo;
                }
        }
        grpbar(rt, tcnt); tcnt += 8;
    }

    // write final h slice to output
    {
        int r0 = rt * 64 + ct * 8;
        const float4* hp = (const float4*)(g_h + (size_t)r0 * 256);
        float4* op = (float4*)(out + (size_t)r0 * 256);
        for (int i = tid; i < 512; i += 256) op[i] = hp[i];
    }
}

// ---------------- launcher -------------------------------------------------
extern "C" void kernel_launch(void* const* d_in, const int* in_sizes, int n_in,
                              void* d_out, int out_size) {
    const float* hs  = (const float*)d_in[0];
    const float* tgt = (const float*)d_in[1];
    const int*   len = (const int*)d_in[2];
    const float* W1  = (const float*)d_in[3];
    const float* b1  = (const float*)d_in[4];
    const float* W2  = (const float*)d_in[5];
    const float* Wr  = (const float*)d_in[6];
    const float* br  = (const float*)d_in[7];
    const float* Wz  = (const float*)d_in[8];
    const float* bz  = (const float*)d_in[9];
    const float* Wn  = (const float*)d_in[10];
    const float* bn  = (const float*)d_in[11];
    float* out = (float*)d_out;
    (void)in_sizes; (void)n_in; (void)out_size;

    cudaFuncSetAttribute(k_recur2, cudaFuncAttributeMaxDynamicSharedMemorySize, 168960);
    cudaFuncSetAttribute(k_scores_mma, cudaFuncAttributeMaxDynamicSharedMemorySize, 110592);
    cudaFuncSetAttribute(k_xproj_mma, cudaFuncAttributeMaxDynamicSharedMemorySize, 40960);

    k_reset<<<1, 32>>>();
    k_cvt_hs<<<51200, 256>>>(hs);
    k_cvt_w<<<896, 256>>>(Wr, Wz, Wn, W1);
    k_tproj<<<B, 128>>>(tgt, W1, b1);
    k_scores_mma<<<1600, 256, 110592>>>(W2);
    k_softmax<<<B, 256>>>(len);
    k_xproj_mma<<<9600, 256, 40960>>>(br, bz, bn);
    k_recur2<<<128, 256, 168960>>>(out);
}

// round 5
// speedup vs baseline: 1.0626x; 1.0626x over previous
#include <cuda_runtime.h>
#include <cuda_bf16.h>
#include <math.h>
#include <stdint.h>

#define B  1024
#define S  200
#define HD 256
#define AD 128

// ---------------- scratch (static device globals; no allocations) ----------
__device__ float g_tproj[B * AD];
__device__ float g_scores[B * S];
__device__ float g_att[S * B];                         // att transposed [t][b]
__device__ __align__(16) float g_X[3ull * S * B * HD]; // [gate][t][b][h]
__device__ __align__(16) float g_z[B * HD];

// bf16 split operands for tensor-core GEMMs
__device__ __align__(16) __nv_bfloat16 g_hsh[(size_t)B * S * HD];
__device__ __align__(16) __nv_bfloat16 g_hsl[(size_t)B * S * HD];
__device__ __align__(16) __nv_bfloat16 g_Wxh[768 * 256];   // [Wr;Wz;Wn] x-part
__device__ __align__(16) __nv_bfloat16 g_Wxl[768 * 256];
__device__ __align__(16) __nv_bfloat16 g_Whh[768 * 256];   // [Wr;Wz;Wn] h-part
__device__ __align__(16) __nv_bfloat16 g_Whl[768 * 256];
__device__ __align__(16) __nv_bfloat16 g_Wsh[128 * 256];   // W1 hidden part
__device__ __align__(16) __nv_bfloat16 g_Wsl[128 * 256];
// recurrence state as bf16 split
__device__ __align__(16) __nv_bfloat16 g_hh[B * HD];
__device__ __align__(16) __nv_bfloat16 g_hl[B * HD];
__device__ __align__(16) __nv_bfloat16 g_rhh[B * HD];
__device__ __align__(16) __nv_bfloat16 g_rhl[B * HD];

static const size_t TB  = (size_t)B * HD;            // 262144
static const size_t XSZ = (size_t)S * B * HD;        // 52,428,800

__device__ __forceinline__ float sigf(float x) { return 1.0f / (1.0f + expf(-x)); }

__device__ __forceinline__ uint32_t smem_u32(const void* p) {
    uint32_t a;
    asm("{ .reg .u64 t; cvta.to.shared.u64 t, %1; cvt.u32.u64 %0, t; }"
        : "=r"(a) : "l"(p));
    return a;
}

__device__ __forceinline__ void ldmat4(uint32_t a[4], uint32_t addr) {
    asm volatile("ldmatrix.sync.aligned.m8n8.x4.shared.b16 {%0,%1,%2,%3}, [%4];"
                 : "=r"(a[0]), "=r"(a[1]), "=r"(a[2]), "=r"(a[3]) : "r"(addr));
}

#define MMA16816(d, a, bb) \
    asm volatile("mma.sync.aligned.m16n8k16.row.col.f32.bf16.bf16.f32 " \
        "{%0,%1,%2,%3}, {%4,%5,%6,%7}, {%8,%9}, {%0,%1,%2,%3};" \
        : "+f"((d)[0]), "+f"((d)[1]), "+f"((d)[2]), "+f"((d)[3]) \
        : "r"((a)[0]), "r"((a)[1]), "r"((a)[2]), "r"((a)[3]), \
          "r"((bb)[0]), "r"((bb)[1]))

#define CLUSTER_SYNC() do { \
    asm volatile("barrier.cluster.arrive.aligned;" ::: "memory"); \
    asm volatile("barrier.cluster.wait.aligned;" ::: "memory"); \
} while (0)

// ---------------- split fp32 -> bf16 hi/lo ----------------------------------
__global__ void k_cvt_hs(const float* __restrict__ hs) {
    size_t i = (size_t)blockIdx.x * 256 + threadIdx.x;   // float4 index
    float4 v = ((const float4*)hs)[i];
    union { __nv_bfloat16 b[4]; uint2 u; } H, L;
    H.b[0] = __float2bfloat16(v.x); L.b[0] = __float2bfloat16(v.x - __bfloat162float(H.b[0]));
    H.b[1] = __float2bfloat16(v.y); L.b[1] = __float2bfloat16(v.y - __bfloat162float(H.b[1]));
    H.b[2] = __float2bfloat16(v.z); L.b[2] = __float2bfloat16(v.z - __bfloat162float(H.b[2]));
    H.b[3] = __float2bfloat16(v.w); L.b[3] = __float2bfloat16(v.w - __bfloat162float(H.b[3]));
    ((uint2*)g_hsh)[i] = H.u;
    ((uint2*)g_hsl)[i] = L.u;
}

__global__ void k_cvt_w(const float* __restrict__ Wr, const float* __restrict__ Wz,
                        const float* __restrict__ Wn, const float* __restrict__ W1) {
    int row = blockIdx.x, k = threadIdx.x;
    if (row < 768) {
        int g = row >> 8, c = row & 255;
        const float* W = (g == 0) ? Wr : (g == 1) ? Wz : Wn;
        float v = W[c * 512 + k];
        __nv_bfloat16 h = __float2bfloat16(v);
        g_Wxh[row * 256 + k] = h;
        g_Wxl[row * 256 + k] = __float2bfloat16(v - __bfloat162float(h));
        float v2 = W[c * 512 + 256 + k];
        __nv_bfloat16 h2 = __float2bfloat16(v2);
        g_Whh[row * 256 + k] = h2;
        g_Whl[row * 256 + k] = __float2bfloat16(v2 - __bfloat162float(h2));
    } else {
        int a = row - 768;
        float v = W1[a * 512 + k];
        __nv_bfloat16 h = __float2bfloat16(v);
        g_Wsh[a * 256 + k] = h;
        g_Wsl[a * 256 + k] = __float2bfloat16(v - __bfloat162float(h));
    }
}

// ---------------- tproj[b,a] = b1[a] + sum_d tgt[b,d]*W1[a,256+d] ----------
__global__ void k_tproj(const float* __restrict__ tgt,
                        const float* __restrict__ W1,
                        const float* __restrict__ b1) {
    __shared__ float4 ts[64];
    int b = blockIdx.x, a = threadIdx.x;
    if (a < 64) ts[a] = ((const float4*)(tgt + (size_t)b * HD))[a];
    __syncthreads();
    const float4* w = (const float4*)(W1 + (size_t)a * 512 + 256);
    float s0 = 0.f, s1 = 0.f, s2 = 0.f, s3 = 0.f;
#pragma unroll
    for (int k = 0; k < 64; k += 4) {
        float4 wv, tv;
        wv = w[k];     tv = ts[k];     s0 += wv.x*tv.x + wv.y*tv.y + wv.z*tv.z + wv.w*tv.w;
        wv = w[k + 1]; tv = ts[k + 1]; s1 += wv.x*tv.x + wv.y*tv.y + wv.z*tv.z + wv.w*tv.w;
        wv = w[k + 2]; tv = ts[k + 2]; s2 += wv.x*tv.x + wv.y*tv.y + wv.z*tv.z + wv.w*tv.w;
        wv = w[k + 3]; tv = ts[k + 3]; s3 += wv.x*tv.x + wv.y*tv.y + wv.z*tv.z + wv.w*tv.w;
    }
    g_tproj[b * AD + a] = b1[a] + ((s0 + s1) + (s2 + s3));
}

// =========== mma.sync bf16-split GEMM mainloop (128x128, Klog=768) =========
__device__ __forceinline__ void gemm_ml(
    const __nv_bfloat16* __restrict__ Ah, const __nv_bfloat16* __restrict__ Al,
    const __nv_bfloat16* __restrict__ Bh, const __nv_bfloat16* __restrict__ Bl,
    __nv_bfloat16* smA, __nv_bfloat16* smB, float c[2][8][4])
{
    int tid = threadIdx.x, lane = tid & 31, wid = tid >> 5;
    int m0 = (wid & 3) * 32, n0 = (wid >> 2) * 64;
    uint32_t smA_u = smem_u32(smA);
    int r0 = tid >> 2, q = tid & 3;

    uint4 ra0, ra1, rb0, rb1;
    ra0 = *(const uint4*)(Ah + r0 * 256 + q * 8);
    ra1 = *(const uint4*)(Ah + (r0 + 64) * 256 + q * 8);
    rb0 = *(const uint4*)(Bh + r0 * 256 + q * 8);
    rb1 = *(const uint4*)(Bh + (r0 + 64) * 256 + q * 8);
    *(uint4*)(smA + r0 * 40 + q * 8)        = ra0;
    *(uint4*)(smA + (r0 + 64) * 40 + q * 8) = ra1;
    *(uint4*)(smB + r0 * 40 + q * 8)        = rb0;
    *(uint4*)(smB + (r0 + 64) * 40 + q * 8) = rb1;
    __syncthreads();

    for (int kc = 0; kc < 24; kc++) {
        if (kc < 23) {
            int kn = kc + 1;
            const __nv_bfloat16* As = (kn < 16) ? Ah : Al;
            const __nv_bfloat16* Bs = (kn < 8) ? Bh : (kn < 16 ? Bl : Bh);
            int k0 = (kn & 7) * 32;
            ra0 = *(const uint4*)(As + r0 * 256 + k0 + q * 8);
            ra1 = *(const uint4*)(As + (r0 + 64) * 256 + k0 + q * 8);
            rb0 = *(const uint4*)(Bs + r0 * 256 + k0 + q * 8);
            rb1 = *(const uint4*)(Bs + (r0 + 64) * 256 + k0 + q * 8);
        }
        const __nv_bfloat16* bufB = smB + (kc & 1) * 5120;
        uint32_t abase = smA_u + (kc & 1) * 10240
                       + (uint32_t)(m0 + (lane & 15)) * 80 + ((lane >> 4) * 8) * 2;
#pragma unroll
        for (int ks = 0; ks < 2; ks++) {
            uint32_t af0[4], af1[4];
            ldmat4(af0, abase + ks * 32);
            ldmat4(af1, abase + 16 * 80 + ks * 32);
            uint32_t bfr[8][2];
#pragma unroll
            for (int nf = 0; nf < 8; nf++) {
                const uint32_t* bp = (const uint32_t*)
                    (bufB + (n0 + nf * 8 + (lane >> 2)) * 40 + ks * 16 + (lane & 3) * 2);
                bfr[nf][0] = bp[0];
                bfr[nf][1] = bp[4];
            }
#pragma unroll
            for (int nf = 0; nf < 8; nf++) {
                MMA16816(c[0][nf], af0, bfr[nf]);
                MMA16816(c[1][nf], af1, bfr[nf]);
            }
        }
        if (kc < 23) {
            int nb = (kc + 1) & 1;
            *(uint4*)(smA + nb * 5120 + r0 * 40 + q * 8)        = ra0;
            *(uint4*)(smA + nb * 5120 + (r0 + 64) * 40 + q * 8) = ra1;
            *(uint4*)(smB + nb * 5120 + r0 * 40 + q * 8)        = rb0;
            *(uint4*)(smB + nb * 5120 + (r0 + 64) * 40 + q * 8) = rb1;
            __syncthreads();
        }
    }
}

// ---------------- X projection via mma.sync --------------------------------
__global__ void __launch_bounds__(256) k_xproj_mma(
    const float* __restrict__ br, const float* __restrict__ bz,
    const float* __restrict__ bn) {
    extern __shared__ __align__(16) char dsm[];
    __nv_bfloat16* smA = (__nv_bfloat16*)dsm;
    __nv_bfloat16* smB = smA + 2 * 5120;
    int ntile = blockIdx.x % 6, mtile = blockIdx.x / 6;

    float c[2][8][4];
#pragma unroll
    for (int i = 0; i < 2; i++)
#pragma unroll
        for (int j = 0; j < 8; j++)
#pragma unroll
            for (int e = 0; e < 4; e++) c[i][j][e] = 0.0f;

    gemm_ml(g_hsh + (size_t)mtile * 128 * 256, g_hsl + (size_t)mtile * 128 * 256,
            g_Wxh + (size_t)ntile * 128 * 256, g_Wxl + (size_t)ntile * 128 * 256,
            smA, smB, c);

    int lane = threadIdx.x & 31, wid = threadIdx.x >> 5;
    int m0 = (wid & 3) * 32, n0 = (wid >> 2) * 64;
    int g = ntile >> 1, h0 = (ntile & 1) * 128;
    const float* bias = (g == 0) ? br : (g == 1) ? bz : bn;
    float2 bv[8];
#pragma unroll
    for (int nf = 0; nf < 8; nf++)
        bv[nf] = *(const float2*)(bias + h0 + n0 + nf * 8 + (lane & 3) * 2);

#pragma unroll
    for (int mf = 0; mf < 2; mf++)
#pragma unroll
        for (int p = 0; p < 2; p++) {
            int rg = mtile * 128 + m0 + mf * 16 + (lane >> 2) + p * 8;
            int b = rg / 200, s = rg - b * 200;
            float* dst = g_X + (size_t)g * XSZ + ((size_t)s * B + b) * 256 + h0;
#pragma unroll
            for (int nf = 0; nf < 8; nf++) {
                float2 o;
                o.x = c[mf][nf][2 * p + 0] + bv[nf].x;
                o.y = c[mf][nf][2 * p + 1] + bv[nf].y;
                *(float2*)(dst + n0 + nf * 8 + (lane & 3) * 2) = o;
            }
        }
}

// ---------------- attention scores via mma.sync ----------------------------
__global__ void __launch_bounds__(256) k_scores_mma(const float* __restrict__ W2) {
    extern __shared__ __align__(16) char dsm[];
    __nv_bfloat16* smA = (__nv_bfloat16*)dsm;
    __nv_bfloat16* smB = smA + 2 * 5120;
    float* Sres = (float*)(dsm + 40960);          // [128][132]
    float* red  = (float*)(dsm + 40960 + 67584);  // [128][2]
    int mtile = blockIdx.x;

    float c[2][8][4];
#pragma unroll
    for (int i = 0; i < 2; i++)
#pragma unroll
        for (int j = 0; j < 8; j++)
#pragma unroll
            for (int e = 0; e < 4; e++) c[i][j][e] = 0.0f;

    gemm_ml(g_hsh + (size_t)mtile * 128 * 256, g_hsl + (size_t)mtile * 128 * 256,
            g_Wsh, g_Wsl, smA, smB, c);

    int tid = threadIdx.x, lane = tid & 31, wid = tid >> 5;
    int m0 = (wid & 3) * 32, n0 = (wid >> 2) * 64;
#pragma unroll
    for (int mf = 0; mf < 2; mf++)
#pragma unroll
        for (int nf = 0; nf < 8; nf++) {
            int r0 = m0 + mf * 16 + (lane >> 2);
            int cc = n0 + nf * 8 + (lane & 3) * 2;
            Sres[r0 * 132 + cc]           = c[mf][nf][0];
            Sres[r0 * 132 + cc + 1]       = c[mf][nf][1];
            Sres[(r0 + 8) * 132 + cc]     = c[mf][nf][2];
            Sres[(r0 + 8) * 132 + cc + 1] = c[mf][nf][3];
        }
    __syncthreads();

    {
        int row = tid >> 1, half = tid & 1;
        int rg = mtile * 128 + row;
        int b = rg / 200;
        const float* tp = g_tproj + b * AD + half * 64;
        const float* w2 = W2 + half * 64;
        float part = 0.0f;
#pragma unroll 8
        for (int j = 0; j < 64; j++)
            part += fmaxf(Sres[row * 132 + half * 64 + j] + tp[j], 0.0f) * w2[j];
        red[row * 2 + half] = part;
    }
    __syncthreads();
    if (tid < 128)
        g_scores[mtile * 128 + tid] = red[tid * 2] + red[tid * 2 + 1];
}

// ---------------- masked softmax over S, output transposed [t][b] ----------
__global__ void k_softmax(const int* __restrict__ lengths) {
    __shared__ float red[256];
    int b = blockIdx.x, s = threadIdx.x;
    int len = lengths[b];
    float sc = -3.0e38f;
    if (s < S) sc = (s < len) ? g_scores[b * S + s] : -1e9f;
    red[s] = sc; __syncthreads();
    for (int o = 128; o; o >>= 1) {
        if (s < o) red[s] = fmaxf(red[s], red[s + o]);
        __syncthreads();
    }
    float mx = red[0]; __syncthreads();
    float e = (s < S) ? expf(sc - mx) : 0.0f;
    red[s] = e; __syncthreads();
    for (int o = 128; o; o >>= 1) {
        if (s < o) red[s] += red[s + o];
        __syncthreads();
    }
    float inv = 1.0f / red[0];
    if (s < S) g_att[s * B + b] = e * inv;
}

// =================== persistent AUGRU scan (mma.sync + clusters) ===========
// 16 clusters (8 CTAs each) = 16 row-groups of 64 batch rows x 8 col-tiles.
// phase1: [r|z](1024x512) = h @ [Wr_h;Wz_h]^T  (CTA tile 64x64)
// phase2: n(1024x256) = rh @ Wn_h^T            (CTA tile 64x32)
#define P1W 16896   // 64*264
#define P2W 8448    // 32*264

__global__ void __launch_bounds__(256, 1) __cluster_dims__(8, 1, 1)
k_recur2(float* __restrict__ out) {
    extern __shared__ __align__(16) __nv_bfloat16 sm[];
    __nv_bfloat16* Wp1h = sm;                    // [64][264]
    __nv_bfloat16* Wp1l = sm + P1W;
    __nv_bfloat16* Wp2h = sm + 2 * P1W;          // [32][264]
    __nv_bfloat16* Wp2l = sm + 2 * P1W + P2W;
    __nv_bfloat16* Ash  = sm + 2 * P1W + 2 * P2W; // [64][264]
    __nv_bfloat16* Asl  = Ash + P1W;

    int tid = threadIdx.x, lane = tid & 31, wid = tid >> 5;
    int bid = blockIdx.x;
    int rt = bid >> 3, ct = bid & 7;
    int mw = wid & 1, nw = wid >> 1;
    int m0w = mw * 32;

    // persistent weights
    for (int i = tid; i < 2048; i += 256) {
        int r = i >> 5, u = i & 31;
        *(uint4*)&Wp1h[r * 264 + u * 8] = *(const uint4*)&g_Whh[(size_t)(ct * 64 + r) * 256 + u * 8];
        *(uint4*)&Wp1l[r * 264 + u * 8] = *(const uint4*)&g_Whl[(size_t)(ct * 64 + r) * 256 + u * 8];
    }
    for (int i = tid; i < 1024; i += 256) {
        int r = i >> 5, u = i & 31;
        *(uint4*)&Wp2h[r * 264 + u * 8] = *(const uint4*)&g_Whh[(size_t)(512 + ct * 32 + r) * 256 + u * 8];
        *(uint4*)&Wp2l[r * 264 + u * 8] = *(const uint4*)&g_Whl[(size_t)(512 + ct * 32 + r) * 256 + u * 8];
    }
    // zero h state (bf16 hi/lo pair is the only h representation)
    {
        int r0 = rt * 64 + ct * 8;
        uint4 zu = make_uint4(0u, 0u, 0u, 0u);
        uint4* hhp = (uint4*)(g_hh + (size_t)r0 * 256);
        uint4* hlp = (uint4*)(g_hl + (size_t)r0 * 256);
        for (int i = tid; i < 256; i += 256) { hhp[i] = zu; hlp[i] = zu; }
    }
    CLUSTER_SYNC();

    uint32_t AshU = smem_u32(Ash), AslU = smem_u32(Asl);
    int rowA = lane >> 2, colq = (lane & 3) * 2;   // epilogue thread layout

    for (int t = 0; t < S; t++) {
        // ---------- step-top prefetch of precomputed operands (DRAM) ------
        float2 xpre[2][2][2];     // phase1 X (r or z path)
        float2 xnpre[2][2];       // phase2 Xn
        float apre[2][2];         // att (z path only)
        {
            const float* Xn = g_X + 2 * XSZ + (size_t)t * TB;
#pragma unroll
            for (int mf = 0; mf < 2; mf++)
#pragma unroll
                for (int p = 0; p < 2; p++) {
                    int m = m0w + mf * 16 + rowA + p * 8;
                    int b = rt * 64 + m;
                    int gcn = ct * 32 + nw * 8 + colq;
                    xnpre[mf][p].x = __ldcg(&Xn[(size_t)b * 256 + gcn]);
                    xnpre[mf][p].y = __ldcg(&Xn[(size_t)b * 256 + gcn + 1]);
                }
            if (ct < 4) {
                const float* Xr = g_X + (size_t)t * TB;
#pragma unroll
                for (int mf = 0; mf < 2; mf++)
#pragma unroll
                    for (int p = 0; p < 2; p++) {
                        int m = m0w + mf * 16 + rowA + p * 8;
                        int b = rt * 64 + m;
#pragma unroll
                        for (int nf = 0; nf < 2; nf++) {
                            int gc = ct * 64 + nw * 16 + nf * 8 + colq;
                            xpre[mf][p][nf].x = __ldcg(&Xr[(size_t)b * 256 + gc]);
                            xpre[mf][p][nf].y = __ldcg(&Xr[(size_t)b * 256 + gc + 1]);
                        }
                    }
            } else {
                const float* Xz = g_X + XSZ + (size_t)t * TB;
#pragma unroll
                for (int mf = 0; mf < 2; mf++)
#pragma unroll
                    for (int p = 0; p < 2; p++) {
                        int m = m0w + mf * 16 + rowA + p * 8;
                        int b = rt * 64 + m;
                        apre[mf][p] = __ldcg(&g_att[t * B + b]);
#pragma unroll
                        for (int nf = 0; nf < 2; nf++) {
                            int gc = (ct - 4) * 64 + nw * 16 + nf * 8 + colq;
                            xpre[mf][p][nf].x = __ldcg(&Xz[(size_t)b * 256 + gc]);
                            xpre[mf][p][nf].y = __ldcg(&Xz[(size_t)b * 256 + gc + 1]);
                        }
                    }
            }
        }

        // ---------- phase 1: load h tile, GEMM 64x64xK768 ----------
        for (int i = tid; i < 2048; i += 256) {
            int r = i >> 5, u = i & 31;
            int4 vh = __ldcg((const int4*)&g_hh[(size_t)(rt * 64 + r) * 256 + u * 8]);
            int4 vl = __ldcg((const int4*)&g_hl[(size_t)(rt * 64 + r) * 256 + u * 8]);
            *(int4*)&Ash[r * 264 + u * 8] = vh;
            *(int4*)&Asl[r * 264 + u * 8] = vl;
        }
        __syncthreads();

        float c1[2][2][4];
#pragma unroll
        for (int i = 0; i < 2; i++)
#pragma unroll
            for (int j = 0; j < 2; j++)
#pragma unroll
                for (int e = 0; e < 4; e++) c1[i][j][e] = 0.0f;
        {
            int n0w = nw * 16;
#pragma unroll
            for (int pass = 0; pass < 3; pass++) {
                uint32_t Abase = (pass == 1) ? AslU : AshU;
                const __nv_bfloat16* Wp = (pass == 2) ? Wp1l : Wp1h;
                uint32_t ab = Abase + (uint32_t)(m0w + (lane & 15)) * 528 + ((lane >> 4) * 8) * 2;
#pragma unroll
                for (int kc = 0; kc < 16; kc++) {
                    int k0 = kc * 16;
                    uint32_t af0[4], af1[4];
                    ldmat4(af0, ab + k0 * 2);
                    ldmat4(af1, ab + 16 * 528 + k0 * 2);
#pragma unroll
                    for (int nf = 0; nf < 2; nf++) {
                        const uint32_t* bp = (const uint32_t*)
                            (Wp + (n0w + nf * 8 + (lane >> 2)) * 264 + k0 + (lane & 3) * 2);
                        uint32_t bf2[2] = { bp[0], bp[4] };
                        MMA16816(c1[0][nf], af0, bf2);
                        MMA16816(c1[1][nf], af1, bf2);
                    }
                }
            }
        }

        // capture this thread's phase-2 h values from the phase-1 smem tile
        float2 hpre[2][2];
#pragma unroll
        for (int mf = 0; mf < 2; mf++)
#pragma unroll
            for (int p = 0; p < 2; p++) {
                int m = m0w + mf * 16 + rowA + p * 8;
                int gcn = ct * 32 + nw * 8 + colq;
                hpre[mf][p].x = __bfloat162float(Ash[m * 264 + gcn])
                              + __bfloat162float(Asl[m * 264 + gcn]);
                hpre[mf][p].y = __bfloat162float(Ash[m * 264 + gcn + 1])
                              + __bfloat162float(Asl[m * 264 + gcn + 1]);
            }

        // ---------- phase 1 epilogue ----------
        if (ct < 4) {
#pragma unroll
            for (int mf = 0; mf < 2; mf++)
#pragma unroll
                for (int p = 0; p < 2; p++) {
                    int m = m0w + mf * 16 + rowA + p * 8;
                    int b = rt * 64 + m;
#pragma unroll
                    for (int nf = 0; nf < 2; nf++) {
                        int gc = ct * 64 + nw * 16 + nf * 8 + colq;
                        float h0 = __bfloat162float(Ash[m * 264 + gc])
                                 + __bfloat162float(Asl[m * 264 + gc]);
                        float h1 = __bfloat162float(Ash[m * 264 + gc + 1])
                                 + __bfloat162float(Asl[m * 264 + gc + 1]);
                        float rh0 = sigf(c1[mf][nf][2 * p] + xpre[mf][p][nf].x) * h0;
                        float rh1 = sigf(c1[mf][nf][2 * p + 1] + xpre[mf][p][nf].y) * h1;
                        __nv_bfloat162 hi, lo;
                        hi.x = __float2bfloat16(rh0);
                        hi.y = __float2bfloat16(rh1);
                        lo.x = __float2bfloat16(rh0 - __bfloat162float(hi.x));
                        lo.y = __float2bfloat16(rh1 - __bfloat162float(hi.y));
                        *(__nv_bfloat162*)&g_rhh[(size_t)b * 256 + gc] = hi;
                        *(__nv_bfloat162*)&g_rhl[(size_t)b * 256 + gc] = lo;
                    }
                }
        } else {
#pragma unroll
            for (int mf = 0; mf < 2; mf++)
#pragma unroll
                for (int p = 0; p < 2; p++) {
                    int m = m0w + mf * 16 + rowA + p * 8;
                    int b = rt * 64 + m;
                    float av = apre[mf][p];
#pragma unroll
                    for (int nf = 0; nf < 2; nf++) {
                        int gc = (ct - 4) * 64 + nw * 16 + nf * 8 + colq;
                        float2 o;
                        o.x = sigf(c1[mf][nf][2 * p] + xpre[mf][p][nf].x) * av;
                        o.y = sigf(c1[mf][nf][2 * p + 1] + xpre[mf][p][nf].y) * av;
                        *(float2*)&g_z[(size_t)b * 256 + gc] = o;
                    }
                }
        }
        CLUSTER_SYNC();

        // ---------- phase 2 prefetch: z (just produced, L2) ----------
        float2 zpre[2][2];
#pragma unroll
        for (int mf = 0; mf < 2; mf++)
#pragma unroll
            for (int p = 0; p < 2; p++) {
                int m = m0w + mf * 16 + rowA + p * 8;
                int b = rt * 64 + m;
                int gcn = ct * 32 + nw * 8 + colq;
                zpre[mf][p].x = __ldcg(&g_z[(size_t)b * 256 + gcn]);
                zpre[mf][p].y = __ldcg(&g_z[(size_t)b * 256 + gcn + 1]);
            }

        // ---------- phase 2: load rh tile, GEMM 64x32xK768 ----------
        for (int i = tid; i < 2048; i += 256) {
            int r = i >> 5, u = i & 31;
            int4 vh = __ldcg((const int4*)&g_rhh[(size_t)(rt * 64 + r) * 256 + u * 8]);
            int4 vl = __ldcg((const int4*)&g_rhl[(size_t)(rt * 64 + r) * 256 + u * 8]);
            *(int4*)&Ash[r * 264 + u * 8] = vh;
            *(int4*)&Asl[r * 264 + u * 8] = vl;
        }
        __syncthreads();

        float c2[2][4];
#pragma unroll
        for (int i = 0; i < 2; i++)
#pragma unroll
            for (int e = 0; e < 4; e++) c2[i][e] = 0.0f;
        {
            int n0w = nw * 8;
#pragma unroll
            for (int pass = 0; pass < 3; pass++) {
                uint32_t Abase = (pass == 1) ? AslU : AshU;
                const __nv_bfloat16* Wp = (pass == 2) ? Wp2l : Wp2h;
                uint32_t ab = Abase + (uint32_t)(m0w + (lane & 15)) * 528 + ((lane >> 4) * 8) * 2;
#pragma unroll
                for (int kc = 0; kc < 16; kc++) {
                    int k0 = kc * 16;
                    uint32_t af0[4], af1[4];
                    ldmat4(af0, ab + k0 * 2);
                    ldmat4(af1, ab + 16 * 528 + k0 * 2);
                    const uint32_t* bp = (const uint32_t*)
                        (Wp + (n0w + (lane >> 2)) * 264 + k0 + (lane & 3) * 2);
                    uint32_t bf2[2] = { bp[0], bp[4] };
                    MMA16816(c2[0], af0, bf2);
                    MMA16816(c2[1], af1, bf2);
                }
            }
        }
        // ---------- phase 2 epilogue: n = tanh(c + Xn); h update ----------
        {
#pragma unroll
            for (int mf = 0; mf < 2; mf++)
#pragma unroll
                for (int p = 0; p < 2; p++) {
                    int m = m0w + mf * 16 + rowA + p * 8;
                    int b = rt * 64 + m;
                    int gc = ct * 32 + nw * 8 + colq;
                    float n0 = tanhf(c2[mf][2 * p] + xnpre[mf][p].x);
                    float n1 = tanhf(c2[mf][2 * p + 1] + xnpre[mf][p].y);
                    float2 hv = hpre[mf][p];
                    float2 zv = zpre[mf][p];
                    float2 o;
                    o.x = hv.x + zv.x * (n0 - hv.x);
                    o.y = hv.y + zv.y * (n1 - hv.y);
                    if (t < S - 1) {
                        __nv_bfloat162 hi, lo;
                        hi.x = __float2bfloat16(o.x);
                        hi.y = __float2bfloat16(o.y);
                        lo.x = __float2bfloat16(o.x - __bfloat162float(hi.x));
                        lo.y = __float2bfloat16(o.y - __bfloat162float(hi.y));
                        *(__nv_bfloat162*)&g_hh[(size_t)b * 256 + gc] = hi;
                        *(__nv_bfloat162*)&g_hl[(size_t)b * 256 + gc] = lo;
                    } else {
                        *(float2*)&out[(size_t)b * 256 + gc] = o;
                    }
                }
        }
        CLUSTER_SYNC();
    }
}

// ---------------- launcher -------------------------------------------------
extern "C" void kernel_launch(void* const* d_in, const int* in_sizes, int n_in,
                              void* d_out, int out_size) {
    const float* hs  = (const float*)d_in[0];
    const float* tgt = (const float*)d_in[1];
    const int*   len = (const int*)d_in[2];
    const float* W1  = (const float*)d_in[3];
    const float* b1  = (const float*)d_in[4];
    const float* W2  = (const float*)d_in[5];
    const float* Wr  = (const float*)d_in[6];
    const float* br  = (const float*)d_in[7];
    const float* Wz  = (const float*)d_in[8];
    const float* bz  = (const float*)d_in[9];
    const float* Wn  = (const float*)d_in[10];
    const float* bn  = (const float*)d_in[11];
    float* out = (float*)d_out;
    (void)in_sizes; (void)n_in; (void)out_size;

    cudaFuncSetAttribute(k_recur2, cudaFuncAttributeMaxDynamicSharedMemorySize, 168960);
    cudaFuncSetAttribute(k_scores_mma, cudaFuncAttributeMaxDynamicSharedMemorySize, 110592);
    cudaFuncSetAttribute(k_xproj_mma, cudaFuncAttributeMaxDynamicSharedMemorySize, 40960);

    k_cvt_hs<<<51200, 256>>>(hs);
    k_cvt_w<<<896, 256>>>(Wr, Wz, Wn, W1);
    k_tproj<<<B, 128>>>(tgt, W1, b1);
    k_scores_mma<<<1600, 256, 110592>>>(W2);
    k_softmax<<<B, 256>>>(len);
    k_xproj_mma<<<9600, 256, 40960>>>(br, bz, bn);
    k_recur2<<<128, 256, 168960>>>(out);
}